// round 5
// baseline (speedup 1.0000x reference)
#include <cuda_runtime.h>
#include <cstdint>

// WindowAttention: B=4096 windows, N=64 tokens, C=128 dim, fp32.
// One CTA per window, 256 threads (8 warps), 2x4 warp grid of 32x32 tiles
// (32x16 for the S GEMM). mma.m16n8k8 tf32, plain smem layouts, single
// reg-staged W buffer. S + softmax partials alias the W region.

#define PX 132   // X/Q/K pitch: A-frag bank 4g+t (conflict-free)
#define PV 136   // V pitch:     B-frag bank 8t+g (conflict-free)
#define PS 68    // S pitch:     A-frag bank 4g+t
#define PW 136   // W pitch:     B-frag bank 8t+g

#define OFF_X  0
#define OFF_Q  (64*PX)
#define OFF_K  (2*64*PX)
#define OFF_V  (3*64*PX)
#define OFF_W  (3*64*PX + 64*PV)   // 34048
#define OFF_S  OFF_W               // S aliases W (dead in between)
#define OFF_PM (OFF_W + 64*PS)     // softmax partials inside W region
#define SMEM_FLOATS (OFF_W + 128*PW)   // 51456
#define SMEM_BYTES  (SMEM_FLOATS * 4)  // 205824

__device__ __forceinline__ float tf32f(float x) {
    uint32_t u;
    asm("cvt.rna.tf32.f32 %0, %1;" : "=r"(u) : "f"(x));
    return __uint_as_float(u);
}

__device__ __forceinline__ void mma8(float acc[4],
                                     uint32_t a0, uint32_t a1, uint32_t a2, uint32_t a3,
                                     uint32_t b0, uint32_t b1) {
    asm volatile(
        "mma.sync.aligned.m16n8k8.row.col.f32.tf32.tf32.f32 "
        "{%0,%1,%2,%3}, {%4,%5,%6,%7}, {%8,%9}, {%0,%1,%2,%3};\n"
        : "+f"(acc[0]), "+f"(acc[1]), "+f"(acc[2]), "+f"(acc[3])
        : "r"(a0), "r"(a1), "r"(a2), "r"(a3), "r"(b0), "r"(b1));
}

__device__ __forceinline__ void bargrp(int id) {
    asm volatile("bar.sync %0, 128;" :: "r"(id) : "memory");
}

__global__ void __launch_bounds__(256, 1)
win_attn_kernel(const float* __restrict__ x,
                const float* __restrict__ wqkv,
                const float* __restrict__ bqkv,
                const float* __restrict__ wproj,
                const float* __restrict__ bproj,
                float* __restrict__ out)
{
    extern __shared__ float smem[];
    float* Xs = smem + OFF_X;
    float* Qs = smem + OFF_Q;   // reused for O
    float* Ks = smem + OFF_K;
    float* Vs = smem + OFF_V;
    float* Ws = smem + OFF_W;
    float* Ss = smem + OFF_S;
    float* Pm = smem + OFF_PM;

    const int tid   = threadIdx.x;
    const int warp  = tid >> 5;
    const int lane  = tid & 31;
    const int g     = lane >> 2;
    const int t     = lane & 3;
    const int wr    = warp & 1;        // 32-row group
    const int wc    = warp >> 1;       // 0..3: 32-col group
    const int mrow  = wr * 32;
    const int nbase = wc * 32;

    const float* xw = x + (size_t)blockIdx.x * 64 * 128;

    // ---------- prologue: X -> smem, W chunk0 -> smem ----------
    #pragma unroll
    for (int s = 0; s < 8; ++s) {
        int i = tid + s * 256;
        float4 v = *(const float4*)(xw + (i >> 5) * 128 + ((i & 31) << 2));
        float* d = Xs + (i >> 5) * PX + ((i & 31) << 2);
        d[0] = tf32f(v.x); d[1] = tf32f(v.y); d[2] = tf32f(v.z); d[3] = tf32f(v.w);
    }
    #pragma unroll
    for (int s = 0; s < 16; ++s) {
        int i = tid + s * 256;
        float4 v = *(const float4*)(wqkv + (i >> 5) * 384 + ((i & 31) << 2));
        float* d = Ws + (i >> 5) * PW + ((i & 31) << 2);
        d[0] = tf32f(v.x); d[1] = tf32f(v.y); d[2] = tf32f(v.z); d[3] = tf32f(v.w);
    }
    __syncthreads();

    // ============ GEMM1: QKV = X @ Wqkv + b, 3 chunks of 128 cols ============
    #pragma unroll
    for (int c = 0; c < 3; ++c) {
        // stage next chunk into regs early (hide latency under MMAs)
        float4 ws4[16];
        if (c < 2) {
            #pragma unroll
            for (int s = 0; s < 16; ++s) {
                int i = tid + s * 256;
                ws4[s] = *(const float4*)(wqkv + (i >> 5) * 384 + (c + 1) * 128 + ((i & 31) << 2));
            }
        }

        float acc[2][4][4];
        #pragma unroll
        for (int m = 0; m < 2; ++m)
            #pragma unroll
            for (int n = 0; n < 4; ++n)
                acc[m][n][0] = acc[m][n][1] = acc[m][n][2] = acc[m][n][3] = 0.f;

        #pragma unroll
        for (int k0 = 0; k0 < 128; k0 += 8) {
            const float* xr0 = Xs + (mrow + g) * PX + k0 + t;
            const float* xr1 = xr0 + 16 * PX;
            uint32_t a00 = __float_as_uint(xr0[0]);
            uint32_t a01 = __float_as_uint(xr0[8 * PX]);
            uint32_t a02 = __float_as_uint(xr0[4]);
            uint32_t a03 = __float_as_uint(xr0[8 * PX + 4]);
            uint32_t a10 = __float_as_uint(xr1[0]);
            uint32_t a11 = __float_as_uint(xr1[8 * PX]);
            uint32_t a12 = __float_as_uint(xr1[4]);
            uint32_t a13 = __float_as_uint(xr1[8 * PX + 4]);
            const float* wrp = Ws + (k0 + t) * PW + nbase + g;
            #pragma unroll
            for (int nt = 0; nt < 4; ++nt) {
                uint32_t b0 = __float_as_uint(wrp[nt * 8]);
                uint32_t b1 = __float_as_uint(wrp[4 * PW + nt * 8]);
                mma8(acc[0][nt], a00, a01, a02, a03, b0, b1);
                mma8(acc[1][nt], a10, a11, a12, a13, b0, b1);
            }
        }

        // epilogue: +bias, tf32-round, scatter to Q/K/V
        float* dst = (c == 0) ? Qs : ((c == 1) ? Ks : Vs);
        const int pad = (c == 2) ? PV : PX;
        #pragma unroll
        for (int m = 0; m < 2; ++m) {
            int r0 = mrow + m * 16 + g;
            #pragma unroll
            for (int nt = 0; nt < 4; ++nt) {
                int j = nbase + nt * 8 + 2 * t;
                float b0 = __ldg(bqkv + c * 128 + j);
                float b1 = __ldg(bqkv + c * 128 + j + 1);
                float2 v0 = make_float2(tf32f(acc[m][nt][0] + b0), tf32f(acc[m][nt][1] + b1));
                float2 v1 = make_float2(tf32f(acc[m][nt][2] + b0), tf32f(acc[m][nt][3] + b1));
                *(float2*)&dst[r0 * pad + j]       = v0;
                *(float2*)&dst[(r0 + 8) * pad + j] = v1;
            }
        }
        __syncthreads();          // all warps done reading Ws for this chunk

        if (c < 2) {
            #pragma unroll
            for (int s = 0; s < 16; ++s) {
                int i = tid + s * 256;
                float* d = Ws + (i >> 5) * PW + ((i & 31) << 2);
                d[0] = tf32f(ws4[s].x); d[1] = tf32f(ws4[s].y);
                d[2] = tf32f(ws4[s].z); d[3] = tf32f(ws4[s].w);
            }
            __syncthreads();
        }
    }

    // ============ GEMM2: S = Q @ K^T (32 rows x 16 cols per warp) ============
    float sacc[2][2][4];
    #pragma unroll
    for (int m = 0; m < 2; ++m)
        #pragma unroll
        for (int n = 0; n < 2; ++n)
            sacc[m][n][0] = sacc[m][n][1] = sacc[m][n][2] = sacc[m][n][3] = 0.f;

    const int sbase = wc * 16;
    #pragma unroll
    for (int k0 = 0; k0 < 128; k0 += 8) {
        const float* qr0 = Qs + (mrow + g) * PX + k0 + t;
        const float* qr1 = qr0 + 16 * PX;
        uint32_t a00 = __float_as_uint(qr0[0]);
        uint32_t a01 = __float_as_uint(qr0[8 * PX]);
        uint32_t a02 = __float_as_uint(qr0[4]);
        uint32_t a03 = __float_as_uint(qr0[8 * PX + 4]);
        uint32_t a10 = __float_as_uint(qr1[0]);
        uint32_t a11 = __float_as_uint(qr1[8 * PX]);
        uint32_t a12 = __float_as_uint(qr1[4]);
        uint32_t a13 = __float_as_uint(qr1[8 * PX + 4]);
        #pragma unroll
        for (int nt = 0; nt < 2; ++nt) {
            const float* kr = Ks + (sbase + nt * 8 + g) * PX + k0 + t;
            uint32_t b0 = __float_as_uint(kr[0]);
            uint32_t b1 = __float_as_uint(kr[4]);
            mma8(sacc[0][nt], a00, a01, a02, a03, b0, b1);
            mma8(sacc[1][nt], a10, a11, a12, a13, b0, b1);
        }
    }

    // ---------- softmax: each row spans the 4 warps with same wr ----------
    const float scale = 0.08838834764831844f;  // 128^-0.5
    const int bid = 1 + wr;
    float mx[2][2];
    #pragma unroll
    for (int m = 0; m < 2; ++m) {
        mx[m][0] = -1e30f; mx[m][1] = -1e30f;
        #pragma unroll
        for (int n = 0; n < 2; ++n) {
            #pragma unroll
            for (int q = 0; q < 4; ++q) sacc[m][n][q] *= scale;
            mx[m][0] = fmaxf(mx[m][0], fmaxf(sacc[m][n][0], sacc[m][n][1]));
            mx[m][1] = fmaxf(mx[m][1], fmaxf(sacc[m][n][2], sacc[m][n][3]));
        }
    }
    #pragma unroll
    for (int m = 0; m < 2; ++m)
        #pragma unroll
        for (int h = 0; h < 2; ++h) {
            mx[m][h] = fmaxf(mx[m][h], __shfl_xor_sync(0xffffffffu, mx[m][h], 1));
            mx[m][h] = fmaxf(mx[m][h], __shfl_xor_sync(0xffffffffu, mx[m][h], 2));
        }
    if (t == 0) {
        #pragma unroll
        for (int m = 0; m < 2; ++m)
            #pragma unroll
            for (int h = 0; h < 2; ++h)
                Pm[(mrow + m * 16 + h * 8 + g) * 4 + wc] = mx[m][h];
    }
    bargrp(bid);
    #pragma unroll
    for (int m = 0; m < 2; ++m)
        #pragma unroll
        for (int h = 0; h < 2; ++h) {
            const float* pr = Pm + (mrow + m * 16 + h * 8 + g) * 4;
            mx[m][h] = fmaxf(fmaxf(pr[0], pr[1]), fmaxf(pr[2], pr[3]));
        }

    float sm[2][2] = {{0.f, 0.f}, {0.f, 0.f}};
    #pragma unroll
    for (int m = 0; m < 2; ++m)
        #pragma unroll
        for (int n = 0; n < 2; ++n) {
            sacc[m][n][0] = __expf(sacc[m][n][0] - mx[m][0]);
            sacc[m][n][1] = __expf(sacc[m][n][1] - mx[m][0]);
            sacc[m][n][2] = __expf(sacc[m][n][2] - mx[m][1]);
            sacc[m][n][3] = __expf(sacc[m][n][3] - mx[m][1]);
            sm[m][0] += sacc[m][n][0] + sacc[m][n][1];
            sm[m][1] += sacc[m][n][2] + sacc[m][n][3];
        }
    #pragma unroll
    for (int m = 0; m < 2; ++m)
        #pragma unroll
        for (int h = 0; h < 2; ++h) {
            sm[m][h] += __shfl_xor_sync(0xffffffffu, sm[m][h], 1);
            sm[m][h] += __shfl_xor_sync(0xffffffffu, sm[m][h], 2);
        }
    if (t == 0) {
        #pragma unroll
        for (int m = 0; m < 2; ++m)
            #pragma unroll
            for (int h = 0; h < 2; ++h)
                Pm[256 + (mrow + m * 16 + h * 8 + g) * 4 + wc] = sm[m][h];
    }
    bargrp(bid);
    float rs[2][2];
    #pragma unroll
    for (int m = 0; m < 2; ++m)
        #pragma unroll
        for (int h = 0; h < 2; ++h) {
            const float* pr = Pm + 256 + (mrow + m * 16 + h * 8 + g) * 4;
            rs[m][h] = 1.f / (pr[0] + pr[1] + pr[2] + pr[3]);
        }

    // P -> S (plain layout, pitch 68)
    #pragma unroll
    for (int m = 0; m < 2; ++m) {
        int r0 = mrow + m * 16 + g;
        #pragma unroll
        for (int nt = 0; nt < 2; ++nt) {
            int j = sbase + nt * 8 + 2 * t;
            float2 v0 = make_float2(tf32f(sacc[m][nt][0] * rs[m][0]),
                                    tf32f(sacc[m][nt][1] * rs[m][0]));
            float2 v1 = make_float2(tf32f(sacc[m][nt][2] * rs[m][1]),
                                    tf32f(sacc[m][nt][3] * rs[m][1]));
            *(float2*)&Ss[r0 * PS + j]       = v0;
            *(float2*)&Ss[(r0 + 8) * PS + j] = v1;
        }
    }
    bargrp(bid);   // this wr-group's S rows complete

    // stage wproj into regs now (hide LDG under GEMM3)
    float4 ws4[16];
    #pragma unroll
    for (int s = 0; s < 16; ++s) {
        int i = tid + s * 256;
        ws4[s] = *(const float4*)(wproj + (i >> 5) * 128 + ((i & 31) << 2));
    }

    // ============ GEMM3: O = P @ V (32 rows x 32 cols per warp) ============
    float oacc[2][4][4];
    #pragma unroll
    for (int m = 0; m < 2; ++m)
        #pragma unroll
        for (int n = 0; n < 4; ++n)
            oacc[m][n][0] = oacc[m][n][1] = oacc[m][n][2] = oacc[m][n][3] = 0.f;

    #pragma unroll
    for (int k0 = 0; k0 < 64; k0 += 8) {
        const float* pr0 = Ss + (mrow + g) * PS + k0 + t;
        const float* pr1 = pr0 + 16 * PS;
        uint32_t a00 = __float_as_uint(pr0[0]);
        uint32_t a01 = __float_as_uint(pr0[8 * PS]);
        uint32_t a02 = __float_as_uint(pr0[4]);
        uint32_t a03 = __float_as_uint(pr0[8 * PS + 4]);
        uint32_t a10 = __float_as_uint(pr1[0]);
        uint32_t a11 = __float_as_uint(pr1[8 * PS]);
        uint32_t a12 = __float_as_uint(pr1[4]);
        uint32_t a13 = __float_as_uint(pr1[8 * PS + 4]);
        const float* vr = Vs + (k0 + t) * PV + nbase + g;
        #pragma unroll
        for (int nt = 0; nt < 4; ++nt) {
            uint32_t b0 = __float_as_uint(vr[nt * 8]);
            uint32_t b1 = __float_as_uint(vr[4 * PV + nt * 8]);
            mma8(oacc[0][nt], a00, a01, a02, a03, b0, b1);
            mma8(oacc[1][nt], a10, a11, a12, a13, b0, b1);
        }
    }

    // store O into Qs (Q dead after GEMM2)
    #pragma unroll
    for (int m = 0; m < 2; ++m) {
        int r0 = mrow + m * 16 + g;
        #pragma unroll
        for (int nt = 0; nt < 4; ++nt) {
            int j = nbase + nt * 8 + 2 * t;
            float2 v0 = make_float2(tf32f(oacc[m][nt][0]), tf32f(oacc[m][nt][1]));
            float2 v1 = make_float2(tf32f(oacc[m][nt][2]), tf32f(oacc[m][nt][3]));
            *(float2*)&Qs[r0 * PX + j]       = v0;
            *(float2*)&Qs[(r0 + 8) * PX + j] = v1;
        }
    }
    __syncthreads();               // all S reads + O writes done
    #pragma unroll
    for (int s = 0; s < 16; ++s) {
        int i = tid + s * 256;
        float* d = Ws + (i >> 5) * PW + ((i & 31) << 2);
        d[0] = tf32f(ws4[s].x); d[1] = tf32f(ws4[s].y);
        d[2] = tf32f(ws4[s].z); d[3] = tf32f(ws4[s].w);
    }
    __syncthreads();

    // ============ GEMM4: out = O @ Wproj + b ============
    float acc[2][4][4];
    #pragma unroll
    for (int m = 0; m < 2; ++m)
        #pragma unroll
        for (int n = 0; n < 4; ++n)
            acc[m][n][0] = acc[m][n][1] = acc[m][n][2] = acc[m][n][3] = 0.f;

    #pragma unroll
    for (int k0 = 0; k0 < 128; k0 += 8) {
        const float* or0 = Qs + (mrow + g) * PX + k0 + t;
        const float* or1 = or0 + 16 * PX;
        uint32_t a00 = __float_as_uint(or0[0]);
        uint32_t a01 = __float_as_uint(or0[8 * PX]);
        uint32_t a02 = __float_as_uint(or0[4]);
        uint32_t a03 = __float_as_uint(or0[8 * PX + 4]);
        uint32_t a10 = __float_as_uint(or1[0]);
        uint32_t a11 = __float_as_uint(or1[8 * PX]);
        uint32_t a12 = __float_as_uint(or1[4]);
        uint32_t a13 = __float_as_uint(or1[8 * PX + 4]);
        const float* wrp = Ws + (k0 + t) * PW + nbase + g;
        #pragma unroll
        for (int nt = 0; nt < 4; ++nt) {
            uint32_t b0 = __float_as_uint(wrp[nt * 8]);
            uint32_t b1 = __float_as_uint(wrp[4 * PW + nt * 8]);
            mma8(acc[0][nt], a00, a01, a02, a03, b0, b1);
            mma8(acc[1][nt], a10, a11, a12, a13, b0, b1);
        }
    }

    float* outw = out + (size_t)blockIdx.x * 64 * 128;
    #pragma unroll
    for (int m = 0; m < 2; ++m) {
        int r0 = mrow + m * 16 + g;
        #pragma unroll
        for (int nt = 0; nt < 4; ++nt) {
            int j = nbase + nt * 8 + 2 * t;
            float b0 = __ldg(bproj + j);
            float b1 = __ldg(bproj + j + 1);
            *(float2*)(outw + r0 * 128 + j) =
                make_float2(acc[m][nt][0] + b0, acc[m][nt][1] + b1);
            *(float2*)(outw + (r0 + 8) * 128 + j) =
                make_float2(acc[m][nt][2] + b0, acc[m][nt][3] + b1);
        }
    }
}

extern "C" void kernel_launch(void* const* d_in, const int* in_sizes, int n_in,
                              void* d_out, int out_size)
{
    const float* x     = (const float*)d_in[0];
    const float* wqkv  = (const float*)d_in[1];
    const float* bqkv  = (const float*)d_in[2];
    const float* wproj = (const float*)d_in[3];
    const float* bproj = (const float*)d_in[4];
    float* out = (float*)d_out;

    const int nwin = in_sizes[0] / (64 * 128);  // 4096

    cudaFuncSetAttribute(win_attn_kernel,
                         cudaFuncAttributeMaxDynamicSharedMemorySize, SMEM_BYTES);

    win_attn_kernel<<<nwin, 256, SMEM_BYTES>>>(x, wqkv, bqkv, wproj, bproj, out);
}

// round 6
// speedup vs baseline: 1.4992x; 1.4992x over previous
#include <cuda_runtime.h>
#include <cstdint>

// WindowAttention: B=4096 windows, N=64 tokens, C=128 dim, fp32.
// One CTA per window, 256 threads (8 warps), 2x4 warp grid of 32x32 tiles
// (32x16 for the S GEMM). mma.m16n8k8 tf32, plain smem layouts.
// Weight staging: LDG AFTER the MMA loop (acc regs dead) -> no spills.

#define PX 132   // X/Q/K pitch: A-frag bank 4g+t (conflict-free)
#define PV 136   // V pitch:     B-frag bank 8t+g (conflict-free)
#define PS 68    // S pitch:     A-frag bank 4g+t
#define PW 136   // W pitch:     B-frag bank 8t+g

#define OFF_X  0
#define OFF_Q  (64*PX)
#define OFF_K  (2*64*PX)
#define OFF_V  (3*64*PX)
#define OFF_W  (3*64*PX + 64*PV)   // 34048
#define OFF_S  OFF_W               // S aliases W (dead in between)
#define OFF_PM (OFF_W + 64*PS)     // softmax partials inside W region
#define SMEM_FLOATS (OFF_W + 128*PW)   // 51456
#define SMEM_BYTES  (SMEM_FLOATS * 4)  // 205824

__device__ __forceinline__ float tf32f(float x) {
    uint32_t u;
    asm("cvt.rna.tf32.f32 %0, %1;" : "=r"(u) : "f"(x));
    return __uint_as_float(u);
}

__device__ __forceinline__ void mma8(float acc[4],
                                     uint32_t a0, uint32_t a1, uint32_t a2, uint32_t a3,
                                     uint32_t b0, uint32_t b1) {
    asm volatile(
        "mma.sync.aligned.m16n8k8.row.col.f32.tf32.tf32.f32 "
        "{%0,%1,%2,%3}, {%4,%5,%6,%7}, {%8,%9}, {%0,%1,%2,%3};\n"
        : "+f"(acc[0]), "+f"(acc[1]), "+f"(acc[2]), "+f"(acc[3])
        : "r"(a0), "r"(a1), "r"(a2), "r"(a3), "r"(b0), "r"(b1));
}

__device__ __forceinline__ void bargrp(int id) {
    asm volatile("bar.sync %0, 128;" :: "r"(id) : "memory");
}

__global__ void __launch_bounds__(256, 1)
win_attn_kernel(const float* __restrict__ x,
                const float* __restrict__ wqkv,
                const float* __restrict__ bqkv,
                const float* __restrict__ wproj,
                const float* __restrict__ bproj,
                float* __restrict__ out)
{
    extern __shared__ float smem[];
    float* Xs = smem + OFF_X;
    float* Qs = smem + OFF_Q;   // reused for O
    float* Ks = smem + OFF_K;
    float* Vs = smem + OFF_V;
    float* Ws = smem + OFF_W;
    float* Ss = smem + OFF_S;
    float* Pm = smem + OFF_PM;

    const int tid   = threadIdx.x;
    const int warp  = tid >> 5;
    const int lane  = tid & 31;
    const int g     = lane >> 2;
    const int t     = lane & 3;
    const int wr    = warp & 1;        // 32-row group
    const int wc    = warp >> 1;       // 0..3: 32-col group
    const int mrow  = wr * 32;
    const int nbase = wc * 32;

    const float* xw = x + (size_t)blockIdx.x * 64 * 128;

    // ---------- prologue: X -> smem, W chunk0 -> smem ----------
    #pragma unroll
    for (int s = 0; s < 8; ++s) {
        int i = tid + s * 256;
        float4 v = *(const float4*)(xw + (i >> 5) * 128 + ((i & 31) << 2));
        float* d = Xs + (i >> 5) * PX + ((i & 31) << 2);
        d[0] = tf32f(v.x); d[1] = tf32f(v.y); d[2] = tf32f(v.z); d[3] = tf32f(v.w);
    }
    #pragma unroll
    for (int s = 0; s < 16; ++s) {
        int i = tid + s * 256;
        float4 v = *(const float4*)(wqkv + (i >> 5) * 384 + ((i & 31) << 2));
        float* d = Ws + (i >> 5) * PW + ((i & 31) << 2);
        d[0] = tf32f(v.x); d[1] = tf32f(v.y); d[2] = tf32f(v.z); d[3] = tf32f(v.w);
    }
    __syncthreads();

    // ============ GEMM1: QKV = X @ Wqkv + b, 3 chunks of 128 cols ============
    #pragma unroll
    for (int c = 0; c < 3; ++c) {
        float acc[2][4][4];
        #pragma unroll
        for (int m = 0; m < 2; ++m)
            #pragma unroll
            for (int n = 0; n < 4; ++n)
                acc[m][n][0] = acc[m][n][1] = acc[m][n][2] = acc[m][n][3] = 0.f;

        #pragma unroll
        for (int k0 = 0; k0 < 128; k0 += 8) {
            const float* xr0 = Xs + (mrow + g) * PX + k0 + t;
            const float* xr1 = xr0 + 16 * PX;
            uint32_t a00 = __float_as_uint(xr0[0]);
            uint32_t a01 = __float_as_uint(xr0[8 * PX]);
            uint32_t a02 = __float_as_uint(xr0[4]);
            uint32_t a03 = __float_as_uint(xr0[8 * PX + 4]);
            uint32_t a10 = __float_as_uint(xr1[0]);
            uint32_t a11 = __float_as_uint(xr1[8 * PX]);
            uint32_t a12 = __float_as_uint(xr1[4]);
            uint32_t a13 = __float_as_uint(xr1[8 * PX + 4]);
            const float* wrp = Ws + (k0 + t) * PW + nbase + g;
            #pragma unroll
            for (int nt = 0; nt < 4; ++nt) {
                uint32_t b0 = __float_as_uint(wrp[nt * 8]);
                uint32_t b1 = __float_as_uint(wrp[4 * PW + nt * 8]);
                mma8(acc[0][nt], a00, a01, a02, a03, b0, b1);
                mma8(acc[1][nt], a10, a11, a12, a13, b0, b1);
            }
        }

        // epilogue: +bias, tf32-round, scatter to Q/K/V  (acc dies here)
        float* dst = (c == 0) ? Qs : ((c == 1) ? Ks : Vs);
        const int pad = (c == 2) ? PV : PX;
        #pragma unroll
        for (int m = 0; m < 2; ++m) {
            int r0 = mrow + m * 16 + g;
            #pragma unroll
            for (int nt = 0; nt < 4; ++nt) {
                int j = nbase + nt * 8 + 2 * t;
                float b0 = __ldg(bqkv + c * 128 + j);
                float b1 = __ldg(bqkv + c * 128 + j + 1);
                float2 v0 = make_float2(tf32f(acc[m][nt][0] + b0), tf32f(acc[m][nt][1] + b1));
                float2 v1 = make_float2(tf32f(acc[m][nt][2] + b0), tf32f(acc[m][nt][3] + b1));
                *(float2*)&dst[r0 * pad + j]       = v0;
                *(float2*)&dst[(r0 + 8) * pad + j] = v1;
            }
        }

        if (c < 2) {
            // stage next chunk NOW (accs dead -> short register live range)
            float4 ws4[16];
            #pragma unroll
            for (int s = 0; s < 16; ++s) {
                int i = tid + s * 256;
                ws4[s] = *(const float4*)(wqkv + (i >> 5) * 384 + (c + 1) * 128 + ((i & 31) << 2));
            }
            __syncthreads();      // all warps done reading Ws for this chunk
            #pragma unroll
            for (int s = 0; s < 16; ++s) {
                int i = tid + s * 256;
                float* d = Ws + (i >> 5) * PW + ((i & 31) << 2);
                d[0] = tf32f(ws4[s].x); d[1] = tf32f(ws4[s].y);
                d[2] = tf32f(ws4[s].z); d[3] = tf32f(ws4[s].w);
            }
            __syncthreads();
        } else {
            __syncthreads();      // Ws region released (S will alias it)
        }
    }

    // ============ GEMM2: S = Q @ K^T (32 rows x 16 cols per warp) ============
    float sacc[2][2][4];
    #pragma unroll
    for (int m = 0; m < 2; ++m)
        #pragma unroll
        for (int n = 0; n < 2; ++n)
            sacc[m][n][0] = sacc[m][n][1] = sacc[m][n][2] = sacc[m][n][3] = 0.f;

    const int sbase = wc * 16;
    #pragma unroll
    for (int k0 = 0; k0 < 128; k0 += 8) {
        const float* qr0 = Qs + (mrow + g) * PX + k0 + t;
        const float* qr1 = qr0 + 16 * PX;
        uint32_t a00 = __float_as_uint(qr0[0]);
        uint32_t a01 = __float_as_uint(qr0[8 * PX]);
        uint32_t a02 = __float_as_uint(qr0[4]);
        uint32_t a03 = __float_as_uint(qr0[8 * PX + 4]);
        uint32_t a10 = __float_as_uint(qr1[0]);
        uint32_t a11 = __float_as_uint(qr1[8 * PX]);
        uint32_t a12 = __float_as_uint(qr1[4]);
        uint32_t a13 = __float_as_uint(qr1[8 * PX + 4]);
        #pragma unroll
        for (int nt = 0; nt < 2; ++nt) {
            const float* kr = Ks + (sbase + nt * 8 + g) * PX + k0 + t;
            uint32_t b0 = __float_as_uint(kr[0]);
            uint32_t b1 = __float_as_uint(kr[4]);
            mma8(sacc[0][nt], a00, a01, a02, a03, b0, b1);
            mma8(sacc[1][nt], a10, a11, a12, a13, b0, b1);
        }
    }

    // ---------- softmax: each row spans the 4 warps with same wr ----------
    const float scale = 0.08838834764831844f;  // 128^-0.5
    const int bid = 1 + wr;
    float mx[2][2];
    #pragma unroll
    for (int m = 0; m < 2; ++m) {
        mx[m][0] = -1e30f; mx[m][1] = -1e30f;
        #pragma unroll
        for (int n = 0; n < 2; ++n) {
            #pragma unroll
            for (int q = 0; q < 4; ++q) sacc[m][n][q] *= scale;
            mx[m][0] = fmaxf(mx[m][0], fmaxf(sacc[m][n][0], sacc[m][n][1]));
            mx[m][1] = fmaxf(mx[m][1], fmaxf(sacc[m][n][2], sacc[m][n][3]));
        }
    }
    #pragma unroll
    for (int m = 0; m < 2; ++m)
        #pragma unroll
        for (int h = 0; h < 2; ++h) {
            mx[m][h] = fmaxf(mx[m][h], __shfl_xor_sync(0xffffffffu, mx[m][h], 1));
            mx[m][h] = fmaxf(mx[m][h], __shfl_xor_sync(0xffffffffu, mx[m][h], 2));
        }
    if (t == 0) {
        #pragma unroll
        for (int m = 0; m < 2; ++m)
            #pragma unroll
            for (int h = 0; h < 2; ++h)
                Pm[(mrow + m * 16 + h * 8 + g) * 4 + wc] = mx[m][h];
    }
    bargrp(bid);
    #pragma unroll
    for (int m = 0; m < 2; ++m)
        #pragma unroll
        for (int h = 0; h < 2; ++h) {
            const float* pr = Pm + (mrow + m * 16 + h * 8 + g) * 4;
            mx[m][h] = fmaxf(fmaxf(pr[0], pr[1]), fmaxf(pr[2], pr[3]));
        }

    float sm[2][2] = {{0.f, 0.f}, {0.f, 0.f}};
    #pragma unroll
    for (int m = 0; m < 2; ++m)
        #pragma unroll
        for (int n = 0; n < 2; ++n) {
            sacc[m][n][0] = __expf(sacc[m][n][0] - mx[m][0]);
            sacc[m][n][1] = __expf(sacc[m][n][1] - mx[m][0]);
            sacc[m][n][2] = __expf(sacc[m][n][2] - mx[m][1]);
            sacc[m][n][3] = __expf(sacc[m][n][3] - mx[m][1]);
            sm[m][0] += sacc[m][n][0] + sacc[m][n][1];
            sm[m][1] += sacc[m][n][2] + sacc[m][n][3];
        }
    #pragma unroll
    for (int m = 0; m < 2; ++m)
        #pragma unroll
        for (int h = 0; h < 2; ++h) {
            sm[m][h] += __shfl_xor_sync(0xffffffffu, sm[m][h], 1);
            sm[m][h] += __shfl_xor_sync(0xffffffffu, sm[m][h], 2);
        }
    if (t == 0) {
        #pragma unroll
        for (int m = 0; m < 2; ++m)
            #pragma unroll
            for (int h = 0; h < 2; ++h)
                Pm[256 + (mrow + m * 16 + h * 8 + g) * 4 + wc] = sm[m][h];
    }
    bargrp(bid);
    float rs[2][2];
    #pragma unroll
    for (int m = 0; m < 2; ++m)
        #pragma unroll
        for (int h = 0; h < 2; ++h) {
            const float* pr = Pm + 256 + (mrow + m * 16 + h * 8 + g) * 4;
            rs[m][h] = 1.f / (pr[0] + pr[1] + pr[2] + pr[3]);
        }

    // P -> S (plain layout, pitch 68)
    #pragma unroll
    for (int m = 0; m < 2; ++m) {
        int r0 = mrow + m * 16 + g;
        #pragma unroll
        for (int nt = 0; nt < 2; ++nt) {
            int j = sbase + nt * 8 + 2 * t;
            float2 v0 = make_float2(tf32f(sacc[m][nt][0] * rs[m][0]),
                                    tf32f(sacc[m][nt][1] * rs[m][0]));
            float2 v1 = make_float2(tf32f(sacc[m][nt][2] * rs[m][1]),
                                    tf32f(sacc[m][nt][3] * rs[m][1]));
            *(float2*)&Ss[r0 * PS + j]       = v0;
            *(float2*)&Ss[(r0 + 8) * PS + j] = v1;
        }
    }
    bargrp(bid);   // this wr-group's S rows complete

    // ============ GEMM3: O = P @ V (32 rows x 32 cols per warp) ============
    float oacc[2][4][4];
    #pragma unroll
    for (int m = 0; m < 2; ++m)
        #pragma unroll
        for (int n = 0; n < 4; ++n)
            oacc[m][n][0] = oacc[m][n][1] = oacc[m][n][2] = oacc[m][n][3] = 0.f;

    #pragma unroll
    for (int k0 = 0; k0 < 64; k0 += 8) {
        const float* pr0 = Ss + (mrow + g) * PS + k0 + t;
        const float* pr1 = pr0 + 16 * PS;
        uint32_t a00 = __float_as_uint(pr0[0]);
        uint32_t a01 = __float_as_uint(pr0[8 * PS]);
        uint32_t a02 = __float_as_uint(pr0[4]);
        uint32_t a03 = __float_as_uint(pr0[8 * PS + 4]);
        uint32_t a10 = __float_as_uint(pr1[0]);
        uint32_t a11 = __float_as_uint(pr1[8 * PS]);
        uint32_t a12 = __float_as_uint(pr1[4]);
        uint32_t a13 = __float_as_uint(pr1[8 * PS + 4]);
        const float* vr = Vs + (k0 + t) * PV + nbase + g;
        #pragma unroll
        for (int nt = 0; nt < 4; ++nt) {
            uint32_t b0 = __float_as_uint(vr[nt * 8]);
            uint32_t b1 = __float_as_uint(vr[4 * PV + nt * 8]);
            mma8(oacc[0][nt], a00, a01, a02, a03, b0, b1);
            mma8(oacc[1][nt], a10, a11, a12, a13, b0, b1);
        }
    }

    // store O into Qs (Q dead after GEMM2)  -- oacc dies here
    #pragma unroll
    for (int m = 0; m < 2; ++m) {
        int r0 = mrow + m * 16 + g;
        #pragma unroll
        for (int nt = 0; nt < 4; ++nt) {
            int j = nbase + nt * 8 + 2 * t;
            float2 v0 = make_float2(tf32f(oacc[m][nt][0]), tf32f(oacc[m][nt][1]));
            float2 v1 = make_float2(tf32f(oacc[m][nt][2]), tf32f(oacc[m][nt][3]));
            *(float2*)&Qs[r0 * PX + j]       = v0;
            *(float2*)&Qs[(r0 + 8) * PX + j] = v1;
        }
    }

    // stage wproj (short live range: issued after oacc is dead)
    {
        float4 ws4[16];
        #pragma unroll
        for (int s = 0; s < 16; ++s) {
            int i = tid + s * 256;
            ws4[s] = *(const float4*)(wproj + (i >> 5) * 128 + ((i & 31) << 2));
        }
        __syncthreads();           // all S reads + O writes done
        #pragma unroll
        for (int s = 0; s < 16; ++s) {
            int i = tid + s * 256;
            float* d = Ws + (i >> 5) * PW + ((i & 31) << 2);
            d[0] = tf32f(ws4[s].x); d[1] = tf32f(ws4[s].y);
            d[2] = tf32f(ws4[s].z); d[3] = tf32f(ws4[s].w);
        }
        __syncthreads();
    }

    // ============ GEMM4: out = O @ Wproj + b ============
    float acc[2][4][4];
    #pragma unroll
    for (int m = 0; m < 2; ++m)
        #pragma unroll
        for (int n = 0; n < 4; ++n)
            acc[m][n][0] = acc[m][n][1] = acc[m][n][2] = acc[m][n][3] = 0.f;

    #pragma unroll
    for (int k0 = 0; k0 < 128; k0 += 8) {
        const float* or0 = Qs + (mrow + g) * PX + k0 + t;
        const float* or1 = or0 + 16 * PX;
        uint32_t a00 = __float_as_uint(or0[0]);
        uint32_t a01 = __float_as_uint(or0[8 * PX]);
        uint32_t a02 = __float_as_uint(or0[4]);
        uint32_t a03 = __float_as_uint(or0[8 * PX + 4]);
        uint32_t a10 = __float_as_uint(or1[0]);
        uint32_t a11 = __float_as_uint(or1[8 * PX]);
        uint32_t a12 = __float_as_uint(or1[4]);
        uint32_t a13 = __float_as_uint(or1[8 * PX + 4]);
        const float* wrp = Ws + (k0 + t) * PW + nbase + g;
        #pragma unroll
        for (int nt = 0; nt < 4; ++nt) {
            uint32_t b0 = __float_as_uint(wrp[nt * 8]);
            uint32_t b1 = __float_as_uint(wrp[4 * PW + nt * 8]);
            mma8(acc[0][nt], a00, a01, a02, a03, b0, b1);
            mma8(acc[1][nt], a10, a11, a12, a13, b0, b1);
        }
    }

    float* outw = out + (size_t)blockIdx.x * 64 * 128;
    #pragma unroll
    for (int m = 0; m < 2; ++m) {
        int r0 = mrow + m * 16 + g;
        #pragma unroll
        for (int nt = 0; nt < 4; ++nt) {
            int j = nbase + nt * 8 + 2 * t;
            float b0 = __ldg(bproj + j);
            float b1 = __ldg(bproj + j + 1);
            *(float2*)(outw + r0 * 128 + j) =
                make_float2(acc[m][nt][0] + b0, acc[m][nt][1] + b1);
            *(float2*)(outw + (r0 + 8) * 128 + j) =
                make_float2(acc[m][nt][2] + b0, acc[m][nt][3] + b1);
        }
    }
}

extern "C" void kernel_launch(void* const* d_in, const int* in_sizes, int n_in,
                              void* d_out, int out_size)
{
    const float* x     = (const float*)d_in[0];
    const float* wqkv  = (const float*)d_in[1];
    const float* bqkv  = (const float*)d_in[2];
    const float* wproj = (const float*)d_in[3];
    const float* bproj = (const float*)d_in[4];
    float* out = (float*)d_out;

    const int nwin = in_sizes[0] / (64 * 128);  // 4096

    cudaFuncSetAttribute(win_attn_kernel,
                         cudaFuncAttributeMaxDynamicSharedMemorySize, SMEM_BYTES);

    win_attn_kernel<<<nwin, 256, SMEM_BYTES>>>(x, wqkv, bqkv, wproj, bproj, out);
}

// round 7
// speedup vs baseline: 1.4993x; 1.0001x over previous
#include <cuda_runtime.h>
#include <cstdint>

// WindowAttention: B=4096 windows, N=64 tokens, C=128 dim, fp32.
// One CTA per window, 256 threads (8 warps), 2x4 warp grid of 32x32 tiles
// (32x16 for the S GEMM). mma.m16n8k8 tf32, plain smem layouts.
// R7: explicit software-pipelined fragment loads (double-buffered regs)
// in all four GEMM mainloops. Weight staging after acc death (R6).

#define PX 132   // X/Q/K pitch: A-frag bank 4g+t (conflict-free)
#define PV 136   // V pitch:     B-frag bank 8t+g (conflict-free)
#define PS 68    // S pitch:     A-frag bank 4g+t
#define PW 136   // W pitch:     B-frag bank 8t+g

#define OFF_X  0
#define OFF_Q  (64*PX)
#define OFF_K  (2*64*PX)
#define OFF_V  (3*64*PX)
#define OFF_W  (3*64*PX + 64*PV)   // 34048
#define OFF_S  OFF_W               // S aliases W (dead in between)
#define OFF_PM (OFF_W + 64*PS)     // softmax partials inside W region
#define SMEM_FLOATS (OFF_W + 128*PW)   // 51456
#define SMEM_BYTES  (SMEM_FLOATS * 4)  // 205824

__device__ __forceinline__ float tf32f(float x) {
    uint32_t u;
    asm("cvt.rna.tf32.f32 %0, %1;" : "=r"(u) : "f"(x));
    return __uint_as_float(u);
}

__device__ __forceinline__ void mma8(float acc[4],
                                     uint32_t a0, uint32_t a1, uint32_t a2, uint32_t a3,
                                     uint32_t b0, uint32_t b1) {
    asm volatile(
        "mma.sync.aligned.m16n8k8.row.col.f32.tf32.tf32.f32 "
        "{%0,%1,%2,%3}, {%4,%5,%6,%7}, {%8,%9}, {%0,%1,%2,%3};\n"
        : "+f"(acc[0]), "+f"(acc[1]), "+f"(acc[2]), "+f"(acc[3])
        : "r"(a0), "r"(a1), "r"(a2), "r"(a3), "r"(b0), "r"(b1));
}

__device__ __forceinline__ void bargrp(int id) {
    asm volatile("bar.sync %0, 128;" :: "r"(id) : "memory");
}

__global__ void __launch_bounds__(256, 1)
win_attn_kernel(const float* __restrict__ x,
                const float* __restrict__ wqkv,
                const float* __restrict__ bqkv,
                const float* __restrict__ wproj,
                const float* __restrict__ bproj,
                float* __restrict__ out)
{
    extern __shared__ float smem[];
    float* Xs = smem + OFF_X;
    float* Qs = smem + OFF_Q;   // reused for O
    float* Ks = smem + OFF_K;
    float* Vs = smem + OFF_V;
    float* Ws = smem + OFF_W;
    float* Ss = smem + OFF_S;
    float* Pm = smem + OFF_PM;

    const int tid   = threadIdx.x;
    const int warp  = tid >> 5;
    const int lane  = tid & 31;
    const int g     = lane >> 2;
    const int t     = lane & 3;
    const int wr    = warp & 1;        // 32-row group
    const int wc    = warp >> 1;       // 0..3: 32-col group
    const int mrow  = wr * 32;
    const int nbase = wc * 32;

    const float* xw = x + (size_t)blockIdx.x * 64 * 128;

    // ---------- prologue: X -> smem, W chunk0 -> smem ----------
    #pragma unroll
    for (int s = 0; s < 8; ++s) {
        int i = tid + s * 256;
        float4 v = *(const float4*)(xw + (i >> 5) * 128 + ((i & 31) << 2));
        float* d = Xs + (i >> 5) * PX + ((i & 31) << 2);
        d[0] = tf32f(v.x); d[1] = tf32f(v.y); d[2] = tf32f(v.z); d[3] = tf32f(v.w);
    }
    #pragma unroll
    for (int s = 0; s < 16; ++s) {
        int i = tid + s * 256;
        float4 v = *(const float4*)(wqkv + (i >> 5) * 384 + ((i & 31) << 2));
        float* d = Ws + (i >> 5) * PW + ((i & 31) << 2);
        d[0] = tf32f(v.x); d[1] = tf32f(v.y); d[2] = tf32f(v.z); d[3] = tf32f(v.w);
    }
    __syncthreads();

    // ============ GEMM1: QKV = X @ Wqkv + b, 3 chunks of 128 cols ============
    #pragma unroll
    for (int c = 0; c < 3; ++c) {
        float acc[2][4][4];
        #pragma unroll
        for (int m = 0; m < 2; ++m)
            #pragma unroll
            for (int n = 0; n < 4; ++n)
                acc[m][n][0] = acc[m][n][1] = acc[m][n][2] = acc[m][n][3] = 0.f;

        {   // pipelined mainloop: 16 k-steps, prefetch depth 1
            const float* xr0 = Xs + (mrow + g) * PX + t;
            const float* xr1 = xr0 + 16 * PX;
            const float* wrp = Ws + t * PW + nbase + g;

            uint32_t Af[2][8], Bf[2][8];
            Af[0][0] = __float_as_uint(xr0[0]);
            Af[0][1] = __float_as_uint(xr0[8 * PX]);
            Af[0][2] = __float_as_uint(xr0[4]);
            Af[0][3] = __float_as_uint(xr0[8 * PX + 4]);
            Af[0][4] = __float_as_uint(xr1[0]);
            Af[0][5] = __float_as_uint(xr1[8 * PX]);
            Af[0][6] = __float_as_uint(xr1[4]);
            Af[0][7] = __float_as_uint(xr1[8 * PX + 4]);
            #pragma unroll
            for (int nt = 0; nt < 4; ++nt) {
                Bf[0][2 * nt]     = __float_as_uint(wrp[nt * 8]);
                Bf[0][2 * nt + 1] = __float_as_uint(wrp[4 * PW + nt * 8]);
            }

            #pragma unroll
            for (int ks = 0; ks < 16; ++ks) {
                const int cur = ks & 1, nxt = cur ^ 1;
                if (ks < 15) {
                    const float* x0 = xr0 + (ks + 1) * 8;
                    const float* x1 = xr1 + (ks + 1) * 8;
                    const float* wp = wrp + (ks + 1) * 8 * PW;
                    Af[nxt][0] = __float_as_uint(x0[0]);
                    Af[nxt][1] = __float_as_uint(x0[8 * PX]);
                    Af[nxt][2] = __float_as_uint(x0[4]);
                    Af[nxt][3] = __float_as_uint(x0[8 * PX + 4]);
                    Af[nxt][4] = __float_as_uint(x1[0]);
                    Af[nxt][5] = __float_as_uint(x1[8 * PX]);
                    Af[nxt][6] = __float_as_uint(x1[4]);
                    Af[nxt][7] = __float_as_uint(x1[8 * PX + 4]);
                    #pragma unroll
                    for (int nt = 0; nt < 4; ++nt) {
                        Bf[nxt][2 * nt]     = __float_as_uint(wp[nt * 8]);
                        Bf[nxt][2 * nt + 1] = __float_as_uint(wp[4 * PW + nt * 8]);
                    }
                }
                #pragma unroll
                for (int nt = 0; nt < 4; ++nt) {
                    mma8(acc[0][nt], Af[cur][0], Af[cur][1], Af[cur][2], Af[cur][3],
                         Bf[cur][2 * nt], Bf[cur][2 * nt + 1]);
                    mma8(acc[1][nt], Af[cur][4], Af[cur][5], Af[cur][6], Af[cur][7],
                         Bf[cur][2 * nt], Bf[cur][2 * nt + 1]);
                }
            }
        }

        // epilogue: +bias, tf32-round, scatter to Q/K/V  (acc dies here)
        float* dst = (c == 0) ? Qs : ((c == 1) ? Ks : Vs);
        const int pad = (c == 2) ? PV : PX;
        #pragma unroll
        for (int m = 0; m < 2; ++m) {
            int r0 = mrow + m * 16 + g;
            #pragma unroll
            for (int nt = 0; nt < 4; ++nt) {
                int j = nbase + nt * 8 + 2 * t;
                float b0 = __ldg(bqkv + c * 128 + j);
                float b1 = __ldg(bqkv + c * 128 + j + 1);
                float2 v0 = make_float2(tf32f(acc[m][nt][0] + b0), tf32f(acc[m][nt][1] + b1));
                float2 v1 = make_float2(tf32f(acc[m][nt][2] + b0), tf32f(acc[m][nt][3] + b1));
                *(float2*)&dst[r0 * pad + j]       = v0;
                *(float2*)&dst[(r0 + 8) * pad + j] = v1;
            }
        }

        if (c < 2) {
            // stage next chunk NOW (accs dead -> short register live range)
            float4 ws4[16];
            #pragma unroll
            for (int s = 0; s < 16; ++s) {
                int i = tid + s * 256;
                ws4[s] = *(const float4*)(wqkv + (i >> 5) * 384 + (c + 1) * 128 + ((i & 31) << 2));
            }
            __syncthreads();      // all warps done reading Ws for this chunk
            #pragma unroll
            for (int s = 0; s < 16; ++s) {
                int i = tid + s * 256;
                float* d = Ws + (i >> 5) * PW + ((i & 31) << 2);
                d[0] = tf32f(ws4[s].x); d[1] = tf32f(ws4[s].y);
                d[2] = tf32f(ws4[s].z); d[3] = tf32f(ws4[s].w);
            }
            __syncthreads();
        } else {
            __syncthreads();      // Ws region released (S will alias it)
        }
    }

    // ============ GEMM2: S = Q @ K^T (32 rows x 16 cols per warp) ============
    float sacc[2][2][4];
    #pragma unroll
    for (int m = 0; m < 2; ++m)
        #pragma unroll
        for (int n = 0; n < 2; ++n)
            sacc[m][n][0] = sacc[m][n][1] = sacc[m][n][2] = sacc[m][n][3] = 0.f;

    const int sbase = wc * 16;
    {   // pipelined mainloop: 16 k-steps
        const float* qr0 = Qs + (mrow + g) * PX + t;
        const float* qr1 = qr0 + 16 * PX;
        const float* kr0 = Ks + (sbase + g) * PX + t;
        const float* kr1 = kr0 + 8 * PX;

        uint32_t Af[2][8], Bf[2][4];
        Af[0][0] = __float_as_uint(qr0[0]);
        Af[0][1] = __float_as_uint(qr0[8 * PX]);
        Af[0][2] = __float_as_uint(qr0[4]);
        Af[0][3] = __float_as_uint(qr0[8 * PX + 4]);
        Af[0][4] = __float_as_uint(qr1[0]);
        Af[0][5] = __float_as_uint(qr1[8 * PX]);
        Af[0][6] = __float_as_uint(qr1[4]);
        Af[0][7] = __float_as_uint(qr1[8 * PX + 4]);
        Bf[0][0] = __float_as_uint(kr0[0]);
        Bf[0][1] = __float_as_uint(kr0[4]);
        Bf[0][2] = __float_as_uint(kr1[0]);
        Bf[0][3] = __float_as_uint(kr1[4]);

        #pragma unroll
        for (int ks = 0; ks < 16; ++ks) {
            const int cur = ks & 1, nxt = cur ^ 1;
            if (ks < 15) {
                const float* q0 = qr0 + (ks + 1) * 8;
                const float* q1 = qr1 + (ks + 1) * 8;
                const float* k0p = kr0 + (ks + 1) * 8;
                const float* k1p = kr1 + (ks + 1) * 8;
                Af[nxt][0] = __float_as_uint(q0[0]);
                Af[nxt][1] = __float_as_uint(q0[8 * PX]);
                Af[nxt][2] = __float_as_uint(q0[4]);
                Af[nxt][3] = __float_as_uint(q0[8 * PX + 4]);
                Af[nxt][4] = __float_as_uint(q1[0]);
                Af[nxt][5] = __float_as_uint(q1[8 * PX]);
                Af[nxt][6] = __float_as_uint(q1[4]);
                Af[nxt][7] = __float_as_uint(q1[8 * PX + 4]);
                Bf[nxt][0] = __float_as_uint(k0p[0]);
                Bf[nxt][1] = __float_as_uint(k0p[4]);
                Bf[nxt][2] = __float_as_uint(k1p[0]);
                Bf[nxt][3] = __float_as_uint(k1p[4]);
            }
            mma8(sacc[0][0], Af[cur][0], Af[cur][1], Af[cur][2], Af[cur][3], Bf[cur][0], Bf[cur][1]);
            mma8(sacc[1][0], Af[cur][4], Af[cur][5], Af[cur][6], Af[cur][7], Bf[cur][0], Bf[cur][1]);
            mma8(sacc[0][1], Af[cur][0], Af[cur][1], Af[cur][2], Af[cur][3], Bf[cur][2], Bf[cur][3]);
            mma8(sacc[1][1], Af[cur][4], Af[cur][5], Af[cur][6], Af[cur][7], Bf[cur][2], Bf[cur][3]);
        }
    }

    // ---------- softmax: each row spans the 4 warps with same wr ----------
    const float scale = 0.08838834764831844f;  // 128^-0.5
    const int bid = 1 + wr;
    float mx[2][2];
    #pragma unroll
    for (int m = 0; m < 2; ++m) {
        mx[m][0] = -1e30f; mx[m][1] = -1e30f;
        #pragma unroll
        for (int n = 0; n < 2; ++n) {
            #pragma unroll
            for (int q = 0; q < 4; ++q) sacc[m][n][q] *= scale;
            mx[m][0] = fmaxf(mx[m][0], fmaxf(sacc[m][n][0], sacc[m][n][1]));
            mx[m][1] = fmaxf(mx[m][1], fmaxf(sacc[m][n][2], sacc[m][n][3]));
        }
    }
    #pragma unroll
    for (int m = 0; m < 2; ++m)
        #pragma unroll
        for (int h = 0; h < 2; ++h) {
            mx[m][h] = fmaxf(mx[m][h], __shfl_xor_sync(0xffffffffu, mx[m][h], 1));
            mx[m][h] = fmaxf(mx[m][h], __shfl_xor_sync(0xffffffffu, mx[m][h], 2));
        }
    if (t == 0) {
        #pragma unroll
        for (int m = 0; m < 2; ++m)
            #pragma unroll
            for (int h = 0; h < 2; ++h)
                Pm[(mrow + m * 16 + h * 8 + g) * 4 + wc] = mx[m][h];
    }
    bargrp(bid);
    #pragma unroll
    for (int m = 0; m < 2; ++m)
        #pragma unroll
        for (int h = 0; h < 2; ++h) {
            const float* pr = Pm + (mrow + m * 16 + h * 8 + g) * 4;
            mx[m][h] = fmaxf(fmaxf(pr[0], pr[1]), fmaxf(pr[2], pr[3]));
        }

    float sm[2][2] = {{0.f, 0.f}, {0.f, 0.f}};
    #pragma unroll
    for (int m = 0; m < 2; ++m)
        #pragma unroll
        for (int n = 0; n < 2; ++n) {
            sacc[m][n][0] = __expf(sacc[m][n][0] - mx[m][0]);
            sacc[m][n][1] = __expf(sacc[m][n][1] - mx[m][0]);
            sacc[m][n][2] = __expf(sacc[m][n][2] - mx[m][1]);
            sacc[m][n][3] = __expf(sacc[m][n][3] - mx[m][1]);
            sm[m][0] += sacc[m][n][0] + sacc[m][n][1];
            sm[m][1] += sacc[m][n][2] + sacc[m][n][3];
        }
    #pragma unroll
    for (int m = 0; m < 2; ++m)
        #pragma unroll
        for (int h = 0; h < 2; ++h) {
            sm[m][h] += __shfl_xor_sync(0xffffffffu, sm[m][h], 1);
            sm[m][h] += __shfl_xor_sync(0xffffffffu, sm[m][h], 2);
        }
    if (t == 0) {
        #pragma unroll
        for (int m = 0; m < 2; ++m)
            #pragma unroll
            for (int h = 0; h < 2; ++h)
                Pm[256 + (mrow + m * 16 + h * 8 + g) * 4 + wc] = sm[m][h];
    }
    bargrp(bid);
    float rs[2][2];
    #pragma unroll
    for (int m = 0; m < 2; ++m)
        #pragma unroll
        for (int h = 0; h < 2; ++h) {
            const float* pr = Pm + 256 + (mrow + m * 16 + h * 8 + g) * 4;
            rs[m][h] = 1.f / (pr[0] + pr[1] + pr[2] + pr[3]);
        }

    // P -> S (plain layout, pitch 68)
    #pragma unroll
    for (int m = 0; m < 2; ++m) {
        int r0 = mrow + m * 16 + g;
        #pragma unroll
        for (int nt = 0; nt < 2; ++nt) {
            int j = sbase + nt * 8 + 2 * t;
            float2 v0 = make_float2(tf32f(sacc[m][nt][0] * rs[m][0]),
                                    tf32f(sacc[m][nt][1] * rs[m][0]));
            float2 v1 = make_float2(tf32f(sacc[m][nt][2] * rs[m][1]),
                                    tf32f(sacc[m][nt][3] * rs[m][1]));
            *(float2*)&Ss[r0 * PS + j]       = v0;
            *(float2*)&Ss[(r0 + 8) * PS + j] = v1;
        }
    }
    bargrp(bid);   // this wr-group's S rows complete

    // ============ GEMM3: O = P @ V (32 rows x 32 cols per warp) ============
    float oacc[2][4][4];
    #pragma unroll
    for (int m = 0; m < 2; ++m)
        #pragma unroll
        for (int n = 0; n < 4; ++n)
            oacc[m][n][0] = oacc[m][n][1] = oacc[m][n][2] = oacc[m][n][3] = 0.f;

    {   // pipelined mainloop: 8 k-steps
        const float* pr0 = Ss + (mrow + g) * PS + t;
        const float* pr1 = pr0 + 16 * PS;
        const float* vr  = Vs + t * PV + nbase + g;

        uint32_t Af[2][8], Bf[2][8];
        Af[0][0] = __float_as_uint(pr0[0]);
        Af[0][1] = __float_as_uint(pr0[8 * PS]);
        Af[0][2] = __float_as_uint(pr0[4]);
        Af[0][3] = __float_as_uint(pr0[8 * PS + 4]);
        Af[0][4] = __float_as_uint(pr1[0]);
        Af[0][5] = __float_as_uint(pr1[8 * PS]);
        Af[0][6] = __float_as_uint(pr1[4]);
        Af[0][7] = __float_as_uint(pr1[8 * PS + 4]);
        #pragma unroll
        for (int nt = 0; nt < 4; ++nt) {
            Bf[0][2 * nt]     = __float_as_uint(vr[nt * 8]);
            Bf[0][2 * nt + 1] = __float_as_uint(vr[4 * PV + nt * 8]);
        }

        #pragma unroll
        for (int ks = 0; ks < 8; ++ks) {
            const int cur = ks & 1, nxt = cur ^ 1;
            if (ks < 7) {
                const float* p0 = pr0 + (ks + 1) * 8;
                const float* p1 = pr1 + (ks + 1) * 8;
                const float* vp = vr + (ks + 1) * 8 * PV;
                Af[nxt][0] = __float_as_uint(p0[0]);
                Af[nxt][1] = __float_as_uint(p0[8 * PS]);
                Af[nxt][2] = __float_as_uint(p0[4]);
                Af[nxt][3] = __float_as_uint(p0[8 * PS + 4]);
                Af[nxt][4] = __float_as_uint(p1[0]);
                Af[nxt][5] = __float_as_uint(p1[8 * PS]);
                Af[nxt][6] = __float_as_uint(p1[4]);
                Af[nxt][7] = __float_as_uint(p1[8 * PS + 4]);
                #pragma unroll
                for (int nt = 0; nt < 4; ++nt) {
                    Bf[nxt][2 * nt]     = __float_as_uint(vp[nt * 8]);
                    Bf[nxt][2 * nt + 1] = __float_as_uint(vp[4 * PV + nt * 8]);
                }
            }
            #pragma unroll
            for (int nt = 0; nt < 4; ++nt) {
                mma8(oacc[0][nt], Af[cur][0], Af[cur][1], Af[cur][2], Af[cur][3],
                     Bf[cur][2 * nt], Bf[cur][2 * nt + 1]);
                mma8(oacc[1][nt], Af[cur][4], Af[cur][5], Af[cur][6], Af[cur][7],
                     Bf[cur][2 * nt], Bf[cur][2 * nt + 1]);
            }
        }
    }

    // store O into Qs (Q dead after GEMM2)  -- oacc dies here
    #pragma unroll
    for (int m = 0; m < 2; ++m) {
        int r0 = mrow + m * 16 + g;
        #pragma unroll
        for (int nt = 0; nt < 4; ++nt) {
            int j = nbase + nt * 8 + 2 * t;
            float2 v0 = make_float2(tf32f(oacc[m][nt][0]), tf32f(oacc[m][nt][1]));
            float2 v1 = make_float2(tf32f(oacc[m][nt][2]), tf32f(oacc[m][nt][3]));
            *(float2*)&Qs[r0 * PX + j]       = v0;
            *(float2*)&Qs[(r0 + 8) * PX + j] = v1;
        }
    }

    // stage wproj (short live range: issued after oacc is dead)
    {
        float4 ws4[16];
        #pragma unroll
        for (int s = 0; s < 16; ++s) {
            int i = tid + s * 256;
            ws4[s] = *(const float4*)(wproj + (i >> 5) * 128 + ((i & 31) << 2));
        }
        __syncthreads();           // all S reads + O writes done
        #pragma unroll
        for (int s = 0; s < 16; ++s) {
            int i = tid + s * 256;
            float* d = Ws + (i >> 5) * PW + ((i & 31) << 2);
            d[0] = tf32f(ws4[s].x); d[1] = tf32f(ws4[s].y);
            d[2] = tf32f(ws4[s].z); d[3] = tf32f(ws4[s].w);
        }
        __syncthreads();
    }

    // ============ GEMM4: out = O @ Wproj + b ============
    float acc[2][4][4];
    #pragma unroll
    for (int m = 0; m < 2; ++m)
        #pragma unroll
        for (int n = 0; n < 4; ++n)
            acc[m][n][0] = acc[m][n][1] = acc[m][n][2] = acc[m][n][3] = 0.f;

    {   // pipelined mainloop: 16 k-steps
        const float* or0 = Qs + (mrow + g) * PX + t;
        const float* or1 = or0 + 16 * PX;
        const float* wrp = Ws + t * PW + nbase + g;

        uint32_t Af[2][8], Bf[2][8];
        Af[0][0] = __float_as_uint(or0[0]);
        Af[0][1] = __float_as_uint(or0[8 * PX]);
        Af[0][2] = __float_as_uint(or0[4]);
        Af[0][3] = __float_as_uint(or0[8 * PX + 4]);
        Af[0][4] = __float_as_uint(or1[0]);
        Af[0][5] = __float_as_uint(or1[8 * PX]);
        Af[0][6] = __float_as_uint(or1[4]);
        Af[0][7] = __float_as_uint(or1[8 * PX + 4]);
        #pragma unroll
        for (int nt = 0; nt < 4; ++nt) {
            Bf[0][2 * nt]     = __float_as_uint(wrp[nt * 8]);
            Bf[0][2 * nt + 1] = __float_as_uint(wrp[4 * PW + nt * 8]);
        }

        #pragma unroll
        for (int ks = 0; ks < 16; ++ks) {
            const int cur = ks & 1, nxt = cur ^ 1;
            if (ks < 15) {
                const float* o0 = or0 + (ks + 1) * 8;
                const float* o1 = or1 + (ks + 1) * 8;
                const float* wp = wrp + (ks + 1) * 8 * PW;
                Af[nxt][0] = __float_as_uint(o0[0]);
                Af[nxt][1] = __float_as_uint(o0[8 * PX]);
                Af[nxt][2] = __float_as_uint(o0[4]);
                Af[nxt][3] = __float_as_uint(o0[8 * PX + 4]);
                Af[nxt][4] = __float_as_uint(o1[0]);
                Af[nxt][5] = __float_as_uint(o1[8 * PX]);
                Af[nxt][6] = __float_as_uint(o1[4]);
                Af[nxt][7] = __float_as_uint(o1[8 * PX + 4]);
                #pragma unroll
                for (int nt = 0; nt < 4; ++nt) {
                    Bf[nxt][2 * nt]     = __float_as_uint(wp[nt * 8]);
                    Bf[nxt][2 * nt + 1] = __float_as_uint(wp[4 * PW + nt * 8]);
                }
            }
            #pragma unroll
            for (int nt = 0; nt < 4; ++nt) {
                mma8(acc[0][nt], Af[cur][0], Af[cur][1], Af[cur][2], Af[cur][3],
                     Bf[cur][2 * nt], Bf[cur][2 * nt + 1]);
                mma8(acc[1][nt], Af[cur][4], Af[cur][5], Af[cur][6], Af[cur][7],
                     Bf[cur][2 * nt], Bf[cur][2 * nt + 1]);
            }
        }
    }

    float* outw = out + (size_t)blockIdx.x * 64 * 128;
    #pragma unroll
    for (int m = 0; m < 2; ++m) {
        int r0 = mrow + m * 16 + g;
        #pragma unroll
        for (int nt = 0; nt < 4; ++nt) {
            int j = nbase + nt * 8 + 2 * t;
            float b0 = __ldg(bproj + j);
            float b1 = __ldg(bproj + j + 1);
            *(float2*)(outw + r0 * 128 + j) =
                make_float2(acc[m][nt][0] + b0, acc[m][nt][1] + b1);
            *(float2*)(outw + (r0 + 8) * 128 + j) =
                make_float2(acc[m][nt][2] + b0, acc[m][nt][3] + b1);
        }
    }
}

extern "C" void kernel_launch(void* const* d_in, const int* in_sizes, int n_in,
                              void* d_out, int out_size)
{
    const float* x     = (const float*)d_in[0];
    const float* wqkv  = (const float*)d_in[1];
    const float* bqkv  = (const float*)d_in[2];
    const float* wproj = (const float*)d_in[3];
    const float* bproj = (const float*)d_in[4];
    float* out = (float*)d_out;

    const int nwin = in_sizes[0] / (64 * 128);  // 4096

    cudaFuncSetAttribute(win_attn_kernel,
                         cudaFuncAttributeMaxDynamicSharedMemorySize, SMEM_BYTES);

    win_attn_kernel<<<nwin, 256, SMEM_BYTES>>>(x, wqkv, bqkv, wproj, bproj, out);
}